// round 11
// baseline (speedup 1.0000x reference)
#include <cuda_runtime.h>
#include <cuda_fp16.h>
#include <cstdint>

typedef __half f16;

constexpr int BSZ = 8, SEQ = 2048, DIM = 768;
constexpr int MTOT = BSZ * SEQ;            // 16384

// Swizzled smem tiles, 64B rows, chunk ^= (row>>1)&3 on 16B chunks.
// CTA tile 128(M) x 256(N): A tile 8KB (128 rows), B tile 16KB (256 rows).
constexpr int AT = 8192;
constexpr int BT = 16384;
constexpr int STB3 = 2 * AT + 2 * BT;      // 49152: Ah,Al,Bh,Bl
constexpr int STB1 = AT + BT;              // 24576: Ah,Bh
constexpr int SMEMSZ3 = 4 * STB3;          // 196608 (4-stage)
constexpr int SMEMSZ1 = 6 * STB1;          // 147456 (6-stage, PV)
// proj V-epilogue staging: 128 x 258 fp32 = 132096 <= SMEMSZ3

// ---------------- static device scratch (allocation-free rule) --------------
__device__ f16 g_xh[(size_t)MTOT * DIM];
__device__ f16 g_xl[(size_t)MTOT * DIM];
__device__ f16 g_wth[3][DIM * DIM];        // contiguous [2304 x 768] B^T
__device__ f16 g_wtl[3][DIM * DIM];
__device__ f16 g_qh[(size_t)MTOT * DIM];
__device__ f16 g_ql[(size_t)MTOT * DIM];
__device__ f16 g_kh[(size_t)MTOT * DIM];
__device__ f16 g_kl[(size_t)MTOT * DIM];
__device__ f16 g_vth[(size_t)MTOT * DIM];   // V^T per batch: [b][768][2048], hi only
__device__ float g_s[(size_t)BSZ * SEQ * SEQ];
__device__ f16 g_ph[(size_t)BSZ * SEQ * SEQ];

// ---------------- PTX helpers ----------------------------------------------
__device__ __forceinline__ uint32_t smem_u32(const void* p) {
    uint32_t a;
    asm("{ .reg .u64 t; cvta.to.shared.u64 t, %1; cvt.u32.u64 %0, t; }"
        : "=r"(a) : "l"(p));
    return a;
}

__device__ __forceinline__ void ldmx4(uint32_t* r, uint32_t a) {
    asm volatile("ldmatrix.sync.aligned.m8n8.x4.shared.b16 {%0,%1,%2,%3}, [%4];"
                 : "=r"(r[0]), "=r"(r[1]), "=r"(r[2]), "=r"(r[3]) : "r"(a));
}

__device__ __forceinline__ void mma_f16(float* c, const uint32_t* a, const uint32_t* b) {
    asm volatile(
        "mma.sync.aligned.m16n8k16.row.col.f32.f16.f16.f32 "
        "{%0,%1,%2,%3}, {%4,%5,%6,%7}, {%8,%9}, {%0,%1,%2,%3};"
        : "+f"(c[0]), "+f"(c[1]), "+f"(c[2]), "+f"(c[3])
        : "r"(a[0]), "r"(a[1]), "r"(a[2]), "r"(a[3]), "r"(b[0]), "r"(b[1]));
}

__device__ __forceinline__ void cpasync16(uint32_t s, const void* g) {
    asm volatile("cp.async.cg.shared.global [%0], [%1], 16;" :: "r"(s), "l"(g));
}

// swizzled in-tile offset for (row, 16B-chunk)
__device__ __forceinline__ uint32_t swz(int row, int ch) {
    return (uint32_t)(row * 64 + ((ch ^ ((row >> 1) & 3)) << 4));
}

// ---------------------------------------------------------------------------
// Fused QKV projection.  256 threads, tile 128x256.  Grid (9, 128).
//   n0 <  768 : Q hi/lo (3-pass)   n0 < 1536 : K hi/lo (3-pass)
//   else      : V^T hi  (2-pass: AhBh + AlBh)
// 4-stage cp.async pipeline (wait_group 2), swizzled smem.
// ---------------------------------------------------------------------------
__global__ void __launch_bounds__(256, 1)
proj_fused(const f16* __restrict__ Ah, const f16* __restrict__ Al,
           const f16* __restrict__ Bh, const f16* __restrict__ Bl,
           f16* __restrict__ Qh, f16* __restrict__ Ql,
           f16* __restrict__ Kh, f16* __restrict__ Kl,
           f16* __restrict__ Vt)
{
    extern __shared__ char smem[];
    const int tid = threadIdx.x, lane = tid & 31, wid = tid >> 5;
    const int m0 = blockIdx.y * 128, n0 = blockIdx.x * 256;
    const int warp_m = wid & 1, warp_n = wid >> 1;    // 2 x 4 warp grid
    const bool three = (n0 < 1536);

    const char* pAh = (const char*)Ah;
    const char* pAl = (const char*)Al;
    const char* pBh = (const char*)Bh;
    const char* pBl = (const char*)Bl;

    const uint32_t sb = smem_u32(smem);
    const uint32_t rowbytes = DIM * 2;

    float acc[4][8][4];
#pragma unroll
    for (int t = 0; t < 4; t++)
#pragma unroll
        for (int j = 0; j < 8; j++)
#pragma unroll
            for (int c = 0; c < 4; c++) acc[t][j][c] = 0.0f;

#define PISSUE(kc, buf)                                                          \
    {                                                                            \
        uint32_t s0 = sb + (buf) * STB3;                                         \
        uint32_t kcb = (uint32_t)(kc) * 64;                                      \
        _Pragma("unroll")                                                        \
        for (int i = 0; i < 2; i++) {                                            \
            int c = tid + i * 256;                                               \
            int r = c >> 2, ch = c & 3;                                          \
            size_t go = (size_t)(m0 + r) * rowbytes + kcb + ch * 16;             \
            uint32_t so = swz(r, ch);                                            \
            cpasync16(s0 + so, pAh + go);                                        \
            cpasync16(s0 + AT + so, pAl + go);                                   \
        }                                                                        \
        _Pragma("unroll")                                                        \
        for (int i = 0; i < 4; i++) {                                            \
            int c = tid + i * 256;                                               \
            int r = c >> 2, ch = c & 3;                                          \
            size_t go = (size_t)(n0 + r) * rowbytes + kcb + ch * 16;             \
            uint32_t so = swz(r, ch);                                            \
            cpasync16(s0 + 2 * AT + so, pBh + go);                               \
            if (three) cpasync16(s0 + 2 * AT + BT + so, pBl + go);               \
        }                                                                        \
        asm volatile("cp.async.commit_group;" ::: "memory");                     \
    }

    PISSUE(0, 0);
    PISSUE(1, 1);
    PISSUE(2, 2);

    const int nch = DIM >> 5;   // 24
    int cb = 0, ib = 3;
    for (int kc = 0; kc < nch; kc++) {
        asm volatile("cp.async.wait_group 2;" ::: "memory");
        __syncthreads();

        const int knext = kc + 3;
        if (knext < nch) PISSUE(knext, ib);
        ib = (ib + 1 == 4) ? 0 : ib + 1;

        const uint32_t sA = sb + cb * STB3;
        cb = (cb + 1 == 4) ? 0 : cb + 1;

#pragma unroll
        for (int ks = 0; ks < 2; ks++) {
            uint32_t afh[4][4], afl[4][4];

            const int ra0 = warp_m * 64 + (lane & 15);
            const int ca = ks * 2 + (lane >> 4);
#pragma unroll
            for (int t = 0; t < 4; t++) {
                uint32_t ad = sA + swz(ra0 + t * 16, ca);
                ldmx4(afh[t], ad);
                ldmx4(afl[t], ad + AT);
            }

            const int rb0 = warp_n * 64 + (lane >> 4) * 8 + (lane & 7);
            const int cbk = ks * 2 + ((lane >> 3) & 1);
#pragma unroll
            for (int jp = 0; jp < 4; jp++) {
                uint32_t bd = sA + 2 * AT + swz(rb0 + jp * 16, cbk);
                uint32_t rh[4];
                ldmx4(rh, bd);
                const int j0 = jp * 2, j1 = jp * 2 + 1;
#pragma unroll
                for (int t = 0; t < 4; t++) {
                    mma_f16(acc[t][j0], afh[t], rh + 0);
                    mma_f16(acc[t][j1], afh[t], rh + 2);
                }
                if (three) {
                    uint32_t rl[4];
                    ldmx4(rl, bd + BT);
#pragma unroll
                    for (int t = 0; t < 4; t++) {
                        mma_f16(acc[t][j0], afh[t], rl + 0);
                        mma_f16(acc[t][j1], afh[t], rl + 2);
                    }
                }
#pragma unroll
                for (int t = 0; t < 4; t++) {
                    mma_f16(acc[t][j0], afl[t], rh + 0);
                    mma_f16(acc[t][j1], afl[t], rh + 2);
                }
            }
        }
        __syncthreads();
    }
#undef PISSUE

    // ---------------- epilogue dispatch ----------------
    const int rbase = warp_m * 64 + (lane >> 2);
    const int cbase = warp_n * 64 + (lane & 3) * 2;

    if (three) {
        f16* Oh = (n0 < 768) ? Qh : Kh;
        f16* Ol = (n0 < 768) ? Ql : Kl;
        const int nc0 = (n0 < 768) ? n0 : n0 - 768;
#pragma unroll
        for (int t = 0; t < 4; t++)
#pragma unroll
            for (int j = 0; j < 8; j++)
#pragma unroll
                for (int h = 0; h < 2; h++) {
                    int rr = m0 + rbase + t * 16 + h * 8;
                    int cc = nc0 + cbase + j * 8;
                    float x0 = acc[t][j][h * 2 + 0], x1 = acc[t][j][h * 2 + 1];
                    f16 h0 = __float2half(x0), h1 = __float2half(x1);
                    f16 l0 = __float2half(x0 - __half2float(h0));
                    f16 l1 = __float2half(x1 - __half2float(h1));
                    *(__half2*)(Oh + (size_t)rr * DIM + cc) = __halves2half2(h0, h1);
                    *(__half2*)(Ol + (size_t)rr * DIM + cc) = __halves2half2(l0, l1);
                }
    } else {
        // V^T: stage 128 x 256 fp32, pitch 258 floats; transposed store.
        float* st = (float*)smem;
#pragma unroll
        for (int t = 0; t < 4; t++)
#pragma unroll
            for (int j = 0; j < 8; j++)
#pragma unroll
                for (int h = 0; h < 2; h++) {
                    int rr = rbase + t * 16 + h * 8;
                    int cc = cbase + j * 8;
                    st[(size_t)rr * 258 + cc + 0] = acc[t][j][h * 2 + 0];
                    st[(size_t)rr * 258 + cc + 1] = acc[t][j][h * 2 + 1];
                }
        __syncthreads();
        const int nv0 = n0 - 1536;
        for (int idx = tid; idx < 128 * 256; idx += 256) {
            int nl = idx >> 7, ml = idx & 127;
            int mg = m0 + ml;
            int b = mg >> 11, mloc = mg & 2047;
            float x = st[(size_t)ml * 258 + nl];
            size_t o = (size_t)b * DIM * SEQ + (size_t)(nv0 + nl) * SEQ + mloc;
            Vt[o] = __float2half(x);
        }
    }
}

// ---------------------------------------------------------------------------
// Batched GEMM, tile 128x256, 256 threads:
//   NPASS=3 (scores, 4-stage) / NPASS=1 (PV, 6-stage), fp32 out.
// ---------------------------------------------------------------------------
template <int NPASS, int NSTAGE>
__global__ void __launch_bounds__(256, 1)
gemm_mma(const f16* __restrict__ Ah, const f16* __restrict__ Al,
         const f16* __restrict__ Bh, const f16* __restrict__ Bl,
         float* __restrict__ O,
         int K, long batchA, long batchB, long batchC, int ldC)
{
    constexpr int STB  = (NPASS == 3) ? STB3 : STB1;
    constexpr int BOFF = (NPASS == 3) ? 2 * AT : AT;

    extern __shared__ char smem[];
    const int tid = threadIdx.x, lane = tid & 31, wid = tid >> 5;
    const int z = blockIdx.z;
    const int m0 = blockIdx.y * 128, n0 = blockIdx.x * 256;
    const int warp_m = wid & 1, warp_n = wid >> 1;

    const char* pAh = (const char*)(Ah + (size_t)z * batchA);
    const char* pAl = (NPASS == 3) ? (const char*)(Al + (size_t)z * batchA) : nullptr;
    const char* pBh = (const char*)(Bh + (size_t)z * batchB);
    const char* pBl = (NPASS == 3) ? (const char*)(Bl + (size_t)z * batchB) : nullptr;

    const uint32_t sb = smem_u32(smem);
    const uint32_t rowbytes = (uint32_t)K * 2;

    float acc[4][8][4];
#pragma unroll
    for (int t = 0; t < 4; t++)
#pragma unroll
        for (int j = 0; j < 8; j++)
#pragma unroll
            for (int c = 0; c < 4; c++) acc[t][j][c] = 0.0f;

    const int nch = K >> 5;

#define ISSUE(kc, buf)                                                           \
    {                                                                            \
        uint32_t s0 = sb + (buf) * STB;                                          \
        uint32_t kcb = (uint32_t)(kc) * 64;                                      \
        _Pragma("unroll")                                                        \
        for (int i = 0; i < 2; i++) {                                            \
            int c = tid + i * 256;                                               \
            int r = c >> 2, ch = c & 3;                                          \
            size_t go = (size_t)(m0 + r) * rowbytes + kcb + ch * 16;             \
            uint32_t so = swz(r, ch);                                            \
            cpasync16(s0 + so, pAh + go);                                        \
            if (NPASS == 3) cpasync16(s0 + AT + so, pAl + go);                   \
        }                                                                        \
        _Pragma("unroll")                                                        \
        for (int i = 0; i < 4; i++) {                                            \
            int c = tid + i * 256;                                               \
            int r = c >> 2, ch = c & 3;                                          \
            size_t go = (size_t)(n0 + r) * rowbytes + kcb + ch * 16;             \
            uint32_t so = swz(r, ch);                                            \
            cpasync16(s0 + BOFF + so, pBh + go);                                 \
            if (NPASS == 3) cpasync16(s0 + BOFF + BT + so, pBl + go);            \
        }                                                                        \
        asm volatile("cp.async.commit_group;" ::: "memory");                     \
    }

#pragma unroll
    for (int p = 0; p < NSTAGE - 1; p++) ISSUE(p, p);

    int cb = 0, ib = NSTAGE - 1;
    for (int kc = 0; kc < nch; kc++) {
        asm volatile("cp.async.wait_group %0;" :: "n"(NSTAGE - 2) : "memory");
        __syncthreads();

        const int knext = kc + NSTAGE - 1;
        if (knext < nch) ISSUE(knext, ib);
        ib = (ib + 1 == NSTAGE) ? 0 : ib + 1;

        const uint32_t sA = sb + cb * STB;
        cb = (cb + 1 == NSTAGE) ? 0 : cb + 1;

#pragma unroll
        for (int ks = 0; ks < 2; ks++) {
            uint32_t afh[4][4], afl[4][4];

            const int ra0 = warp_m * 64 + (lane & 15);
            const int ca = ks * 2 + (lane >> 4);
#pragma unroll
            for (int t = 0; t < 4; t++) {
                uint32_t ad = sA + swz(ra0 + t * 16, ca);
                ldmx4(afh[t], ad);
                if (NPASS == 3) ldmx4(afl[t], ad + AT);
            }

            const int rb0 = warp_n * 64 + (lane >> 4) * 8 + (lane & 7);
            const int cbk = ks * 2 + ((lane >> 3) & 1);
#pragma unroll
            for (int jp = 0; jp < 4; jp++) {
                uint32_t bd = sA + BOFF + swz(rb0 + jp * 16, cbk);
                uint32_t rh[4];
                ldmx4(rh, bd);
                const int j0 = jp * 2, j1 = jp * 2 + 1;
#pragma unroll
                for (int t = 0; t < 4; t++) {
                    mma_f16(acc[t][j0], afh[t], rh + 0);
                    mma_f16(acc[t][j1], afh[t], rh + 2);
                }
                if (NPASS == 3) {
                    uint32_t rl[4];
                    ldmx4(rl, bd + BT);
#pragma unroll
                    for (int t = 0; t < 4; t++) {
                        mma_f16(acc[t][j0], afh[t], rl + 0);
                        mma_f16(acc[t][j1], afh[t], rl + 2);
                    }
#pragma unroll
                    for (int t = 0; t < 4; t++) {
                        mma_f16(acc[t][j0], afl[t], rh + 0);
                        mma_f16(acc[t][j1], afl[t], rh + 2);
                    }
                }
            }
        }
        __syncthreads();
    }
#undef ISSUE

    // fp32 epilogue
    const int rbase = warp_m * 64 + (lane >> 2);
    const int cbase = warp_n * 64 + (lane & 3) * 2;
    float* C = O + (size_t)z * batchC;
#pragma unroll
    for (int t = 0; t < 4; t++)
#pragma unroll
        for (int j = 0; j < 8; j++) {
            int rr = m0 + rbase + t * 16;
            int cc = n0 + cbase + j * 8;
            *(float2*)(C + (size_t)rr * ldC + cc) =
                make_float2(acc[t][j][0], acc[t][j][1]);
            *(float2*)(C + (size_t)(rr + 8) * ldC + cc) =
                make_float2(acc[t][j][2], acc[t][j][3]);
        }
}

// ---------------- prep kernels ----------------------------------------------
__global__ void split_kernel(const float* __restrict__ X,
                             f16* __restrict__ H, f16* __restrict__ L, int n)
{
    int i = blockIdx.x * 256 + threadIdx.x;
    if (i < n) {
        float x = X[i];
        f16 h = __float2half(x);
        H[i] = h;
        L[i] = __float2half(x - __half2float(h));
    }
}

__global__ void wsplit_kernel(const float* __restrict__ W,
                              f16* __restrict__ TH, f16* __restrict__ TL)
{
    int i = blockIdx.x * 256 + threadIdx.x;   // out idx f*DIM + d
    int f = i / DIM, d = i % DIM;
    float x = W[d * DIM + f];
    f16 h = __float2half(x);
    TH[i] = h;
    TL[i] = __float2half(x - __half2float(h));
}

// ---------------- softmax: S fp32 -> P fp16 hi (vectorized) -----------------
__global__ void __launch_bounds__(256)
softmax_kernel(const float* __restrict__ S, f16* __restrict__ Ph)
{
    const int row = blockIdx.x;
    const float4* p4 = (const float4*)(S + (size_t)row * SEQ);
    const int tid = threadIdx.x;

    float4 va = p4[tid];
    float4 vb = p4[tid + 256];
    float m = fmaxf(fmaxf(fmaxf(va.x, va.y), fmaxf(va.z, va.w)),
                    fmaxf(fmaxf(vb.x, vb.y), fmaxf(vb.z, vb.w)));

    __shared__ float red[256];
    red[tid] = m;
    __syncthreads();
#pragma unroll
    for (int s = 128; s > 0; s >>= 1) {
        if (tid < s) red[tid] = fmaxf(red[tid], red[tid + s]);
        __syncthreads();
    }
    m = red[0];
    __syncthreads();

    va.x = expf(va.x - m); va.y = expf(va.y - m);
    va.z = expf(va.z - m); va.w = expf(va.w - m);
    vb.x = expf(vb.x - m); vb.y = expf(vb.y - m);
    vb.z = expf(vb.z - m); vb.w = expf(vb.w - m);
    float sum = (va.x + va.y) + (va.z + va.w) + (vb.x + vb.y) + (vb.z + vb.w);

    red[tid] = sum;
    __syncthreads();
#pragma unroll
    for (int s = 128; s > 0; s >>= 1) {
        if (tid < s) red[tid] += red[tid + s];
        __syncthreads();
    }
    const float inv = 1.0f / red[0];

    __half2* ph2 = (__half2*)(Ph + (size_t)row * SEQ);
#pragma unroll
    for (int half = 0; half < 2; half++) {
        float4 v = half ? vb : va;
        int base = (half ? (tid + 256) : tid) * 2;
        ph2[base + 0] = __halves2half2(__float2half(v.x * inv),
                                       __float2half(v.y * inv));
        ph2[base + 1] = __halves2half2(__float2half(v.z * inv),
                                       __float2half(v.w * inv));
    }
}

// ---------------------------------------------------------------------------
extern "C" void kernel_launch(void* const* d_in, const int* in_sizes, int n_in,
                              void* d_out, int out_size)
{
    const float* X  = (const float*)d_in[0];
    const float* Wq = (const float*)d_in[1];
    const float* Wk = (const float*)d_in[2];
    const float* Wv = (const float*)d_in[3];
    float* out = (float*)d_out;

    f16 *xh, *xl, *wth, *wtl, *qh, *ql, *kh, *kl, *vth, *ph;
    float* s;
    cudaGetSymbolAddress((void**)&xh, g_xh);
    cudaGetSymbolAddress((void**)&xl, g_xl);
    cudaGetSymbolAddress((void**)&wth, g_wth);
    cudaGetSymbolAddress((void**)&wtl, g_wtl);
    cudaGetSymbolAddress((void**)&qh, g_qh);
    cudaGetSymbolAddress((void**)&ql, g_ql);
    cudaGetSymbolAddress((void**)&kh, g_kh);
    cudaGetSymbolAddress((void**)&kl, g_kl);
    cudaGetSymbolAddress((void**)&vth, g_vth);
    cudaGetSymbolAddress((void**)&ph, g_ph);
    cudaGetSymbolAddress((void**)&s, g_s);

    cudaFuncSetAttribute(proj_fused, cudaFuncAttributeMaxDynamicSharedMemorySize, SMEMSZ3);
    cudaFuncSetAttribute(gemm_mma<3, 4>, cudaFuncAttributeMaxDynamicSharedMemorySize, SMEMSZ3);
    cudaFuncSetAttribute(gemm_mma<1, 6>, cudaFuncAttributeMaxDynamicSharedMemorySize, SMEMSZ1);

    const int nx = MTOT * DIM;
    split_kernel<<<nx / 256, 256>>>(X, xh, xl, nx);
    wsplit_kernel<<<(DIM * DIM) / 256, 256>>>(Wq, wth + 0 * DIM * DIM, wtl + 0 * DIM * DIM);
    wsplit_kernel<<<(DIM * DIM) / 256, 256>>>(Wk, wth + 1 * DIM * DIM, wtl + 1 * DIM * DIM);
    wsplit_kernel<<<(DIM * DIM) / 256, 256>>>(Wv, wth + 2 * DIM * DIM, wtl + 2 * DIM * DIM);

    // Fused QKV projection: grid 9 x 128 (tiles of 256 cols over [Q|K|V])
    dim3 gp(9, MTOT / 128, 1);
    proj_fused<<<gp, 256, SMEMSZ3>>>(xh, xl, wth, wtl, qh, ql, kh, kl, vth);

    // Scores: per batch S = Q * K^T, [2048,2048], K=768 (3-pass, 4-stage)
    dim3 gs(SEQ / 256, SEQ / 128, BSZ);
    gemm_mma<3, 4><<<gs, 256, SMEMSZ3>>>(qh, ql, kh, kl, s, DIM,
                                         (long)SEQ * DIM, (long)SEQ * DIM,
                                         (long)SEQ * SEQ, SEQ);

    softmax_kernel<<<BSZ * SEQ, 256>>>(s, ph);

    // Out: per batch O = P * (V^T)^T, [2048,768], K=2048 (1-pass, 6-stage)
    dim3 go(DIM / 256, SEQ / 128, BSZ);
    gemm_mma<1, 6><<<go, 256, SMEMSZ1>>>(ph, nullptr, vth, nullptr, out, SEQ,
                                         (long)SEQ * SEQ, (long)DIM * SEQ,
                                         (long)SEQ * DIM, DIM);
}

// round 12
// speedup vs baseline: 1.1395x; 1.1395x over previous
#include <cuda_runtime.h>
#include <cuda_fp16.h>
#include <cstdint>

typedef __half f16;

constexpr int BSZ = 8, SEQ = 2048, DIM = 768;
constexpr int MTOT = BSZ * SEQ;            // 16384

// Swizzled smem tiles: 128 rows x 64B, chunk ^= (row>>1)&3  (16B chunks).
constexpr int TILE  = 8192;
constexpr int STB3  = 4 * TILE;            // 32768: Ah,Al,Bh,Bl
constexpr int STB1  = 2 * TILE;            // 16384: Ah,Bh (PV)
constexpr int SMEMSZ3 = 3 * STB3;          // 98304 (3-stage)
constexpr int SMEMSZ1 = 6 * STB1;          // 98304 (6-stage, PV)
// epi2 staging needs 128*129*4 = 66048 <= both

// ---------------- static device scratch (allocation-free rule) --------------
__device__ f16 g_xh[(size_t)MTOT * DIM];
__device__ f16 g_xl[(size_t)MTOT * DIM];
__device__ f16 g_wth[3][DIM * DIM];        // contiguous [2304 x 768] B^T
__device__ f16 g_wtl[3][DIM * DIM];
__device__ f16 g_qh[(size_t)MTOT * DIM];
__device__ f16 g_ql[(size_t)MTOT * DIM];
__device__ f16 g_kh[(size_t)MTOT * DIM];
__device__ f16 g_kl[(size_t)MTOT * DIM];
__device__ f16 g_vth[(size_t)MTOT * DIM];   // V^T per batch: [b][768][2048], hi only
__device__ float g_s[(size_t)BSZ * SEQ * SEQ];
__device__ f16 g_ph[(size_t)BSZ * SEQ * SEQ];

// ---------------- PTX helpers ----------------------------------------------
__device__ __forceinline__ uint32_t smem_u32(const void* p) {
    uint32_t a;
    asm("{ .reg .u64 t; cvta.to.shared.u64 t, %1; cvt.u32.u64 %0, t; }"
        : "=r"(a) : "l"(p));
    return a;
}

__device__ __forceinline__ void ldmx4(uint32_t* r, uint32_t a) {
    asm volatile("ldmatrix.sync.aligned.m8n8.x4.shared.b16 {%0,%1,%2,%3}, [%4];"
                 : "=r"(r[0]), "=r"(r[1]), "=r"(r[2]), "=r"(r[3]) : "r"(a));
}

__device__ __forceinline__ void mma_f16(float* c, const uint32_t* a, const uint32_t* b) {
    asm volatile(
        "mma.sync.aligned.m16n8k16.row.col.f32.f16.f16.f32 "
        "{%0,%1,%2,%3}, {%4,%5,%6,%7}, {%8,%9}, {%0,%1,%2,%3};"
        : "+f"(c[0]), "+f"(c[1]), "+f"(c[2]), "+f"(c[3])
        : "r"(a[0]), "r"(a[1]), "r"(a[2]), "r"(a[3]), "r"(b[0]), "r"(b[1]));
}

__device__ __forceinline__ void cpasync16(uint32_t s, const void* g) {
    asm volatile("cp.async.cg.shared.global [%0], [%1], 16;" :: "r"(s), "l"(g));
}

// swizzled in-tile offset for (row, 16B-chunk)
__device__ __forceinline__ uint32_t swz(int row, int ch) {
    return (uint32_t)(row * 64 + ((ch ^ ((row >> 1) & 3)) << 4));
}

// ---------------------------------------------------------------------------
// Fused QKV projection.  Grid (18, 128); n0 selects output + pass count:
//   n0 <  768 : Q hi/lo (3-pass)   n0 < 1536 : K hi/lo (3-pass)
//   else      : V^T hi  (2-pass)
// 3-stage cp.async pipeline, swizzled smem.  128 threads, 2 CTAs/SM.
// ---------------------------------------------------------------------------
__global__ void __launch_bounds__(128, 2)
proj_fused(const f16* __restrict__ Ah, const f16* __restrict__ Al,
           const f16* __restrict__ Bh, const f16* __restrict__ Bl,
           f16* __restrict__ Qh, f16* __restrict__ Ql,
           f16* __restrict__ Kh, f16* __restrict__ Kl,
           f16* __restrict__ Vt)
{
    extern __shared__ char smem[];
    const int tid = threadIdx.x, lane = tid & 31, wid = tid >> 5;
    const int m0 = blockIdx.y * 128, n0 = blockIdx.x * 128;
    const int warp_m = wid & 1, warp_n = wid >> 1;
    const bool three = (n0 < 1536);

    const char* pAh = (const char*)Ah;
    const char* pAl = (const char*)Al;
    const char* pBh = (const char*)Bh;
    const char* pBl = (const char*)Bl;

    const uint32_t sb = smem_u32(smem);
    const uint32_t rowbytes = DIM * 2;

    float acc[4][8][4];
#pragma unroll
    for (int t = 0; t < 4; t++)
#pragma unroll
        for (int j = 0; j < 8; j++)
#pragma unroll
            for (int c = 0; c < 4; c++) acc[t][j][c] = 0.0f;

#define PISSUE(kc, buf)                                                          \
    {                                                                            \
        uint32_t s0 = sb + (buf) * STB3;                                         \
        uint32_t kcb = (uint32_t)(kc) * 64;                                      \
        _Pragma("unroll")                                                        \
        for (int i = 0; i < 4; i++) {                                            \
            int c = tid + i * 128;                                               \
            int r = c >> 2, ch = c & 3;                                          \
            size_t goA = (size_t)(m0 + r) * rowbytes + kcb + ch * 16;            \
            size_t goB = (size_t)(n0 + r) * rowbytes + kcb + ch * 16;            \
            uint32_t so = swz(r, ch);                                            \
            cpasync16(s0 + 0 * TILE + so, pAh + goA);                            \
            cpasync16(s0 + 1 * TILE + so, pAl + goA);                            \
            cpasync16(s0 + 2 * TILE + so, pBh + goB);                            \
            if (three) cpasync16(s0 + 3 * TILE + so, pBl + goB);                 \
        }                                                                        \
        asm volatile("cp.async.commit_group;" ::: "memory");                     \
    }

    PISSUE(0, 0);
    PISSUE(1, 1);

    const int nch = DIM >> 5;   // 24
    int cb = 0, ib = 2;
    for (int kc = 0; kc < nch; kc++) {
        asm volatile("cp.async.wait_group 1;" ::: "memory");
        __syncthreads();

        const int knext = kc + 2;
        if (knext < nch) PISSUE(knext, ib);
        ib = (ib + 1 == 3) ? 0 : ib + 1;

        const uint32_t sA = sb + cb * STB3;
        cb = (cb + 1 == 3) ? 0 : cb + 1;

#pragma unroll
        for (int ks = 0; ks < 2; ks++) {
            uint32_t afh[4][4], afl[4][4];

            const int ra0 = warp_m * 64 + (lane & 15);
            const int ca = ks * 2 + (lane >> 4);
#pragma unroll
            for (int t = 0; t < 4; t++) {
                uint32_t ad = sA + swz(ra0 + t * 16, ca);
                ldmx4(afh[t], ad);
                ldmx4(afl[t], ad + TILE);
            }

            const int rb0 = warp_n * 64 + (lane >> 4) * 8 + (lane & 7);
            const int cbk = ks * 2 + ((lane >> 3) & 1);
#pragma unroll
            for (int jp = 0; jp < 4; jp++) {
                uint32_t bd = sA + 2 * TILE + swz(rb0 + jp * 16, cbk);
                uint32_t rh[4];
                ldmx4(rh, bd);
                const int j0 = jp * 2, j1 = jp * 2 + 1;
#pragma unroll
                for (int t = 0; t < 4; t++) {
                    mma_f16(acc[t][j0], afh[t], rh + 0);
                    mma_f16(acc[t][j1], afh[t], rh + 2);
                }
                if (three) {
                    uint32_t rl[4];
                    ldmx4(rl, bd + TILE);
#pragma unroll
                    for (int t = 0; t < 4; t++) {
                        mma_f16(acc[t][j0], afh[t], rl + 0);
                        mma_f16(acc[t][j1], afh[t], rl + 2);
                    }
                }
#pragma unroll
                for (int t = 0; t < 4; t++) {
                    mma_f16(acc[t][j0], afl[t], rh + 0);
                    mma_f16(acc[t][j1], afl[t], rh + 2);
                }
            }
        }
        __syncthreads();
    }
#undef PISSUE

    // ---------------- epilogue dispatch ----------------
    const int rbase = warp_m * 64 + (lane >> 2);
    const int cbase = warp_n * 64 + (lane & 3) * 2;

    if (three) {
        f16* Oh = (n0 < 768) ? Qh : Kh;
        f16* Ol = (n0 < 768) ? Ql : Kl;
        const int nc0 = (n0 < 768) ? n0 : n0 - 768;
#pragma unroll
        for (int t = 0; t < 4; t++)
#pragma unroll
            for (int j = 0; j < 8; j++)
#pragma unroll
                for (int h = 0; h < 2; h++) {
                    int rr = m0 + rbase + t * 16 + h * 8;
                    int cc = nc0 + cbase + j * 8;
                    float x0 = acc[t][j][h * 2 + 0], x1 = acc[t][j][h * 2 + 1];
                    f16 h0 = __float2half(x0), h1 = __float2half(x1);
                    f16 l0 = __float2half(x0 - __half2float(h0));
                    f16 l1 = __float2half(x1 - __half2float(h1));
                    *(__half2*)(Oh + (size_t)rr * DIM + cc) = __halves2half2(h0, h1);
                    *(__half2*)(Ol + (size_t)rr * DIM + cc) = __halves2half2(l0, l1);
                }
    } else {
        float* st = (float*)smem;
#pragma unroll
        for (int t = 0; t < 4; t++)
#pragma unroll
            for (int j = 0; j < 8; j++)
#pragma unroll
                for (int h = 0; h < 2; h++) {
                    int rr = rbase + t * 16 + h * 8;
                    int cc = cbase + j * 8;
                    st[(size_t)rr * 129 + cc + 0] = acc[t][j][h * 2 + 0];
                    st[(size_t)rr * 129 + cc + 1] = acc[t][j][h * 2 + 1];
                }
        __syncthreads();
        const int nv0 = n0 - 1536;
        for (int idx = tid; idx < 128 * 128; idx += 128) {
            int nl = idx >> 7, ml = idx & 127;
            int mg = m0 + ml;
            int b = mg >> 11, mloc = mg & 2047;
            float x = st[(size_t)ml * 129 + nl];
            size_t o = (size_t)b * DIM * SEQ + (size_t)(nv0 + nl) * SEQ + mloc;
            Vt[o] = __float2half(x);
        }
    }
}

// ---------------------------------------------------------------------------
// Batched GEMM: NPASS=3 (scores, 3-stage) / NPASS=1 (PV, 6-stage), fp32 out.
// 128 threads, tile 128x128, warp tile 64x64, 2 CTAs/SM.
// ---------------------------------------------------------------------------
template <int NPASS, int NSTAGE>
__global__ void __launch_bounds__(128, 2)
gemm_mma(const f16* __restrict__ Ah, const f16* __restrict__ Al,
         const f16* __restrict__ Bh, const f16* __restrict__ Bl,
         float* __restrict__ O,
         int K, long batchA, long batchB, long batchC, int ldC)
{
    constexpr int STB  = (NPASS == 1) ? STB1 : STB3;
    constexpr int BOFF = (NPASS == 1) ? TILE : 2 * TILE;   // B_HI offset

    extern __shared__ char smem[];
    const int tid = threadIdx.x, lane = tid & 31, wid = tid >> 5;
    const int z = blockIdx.z;
    const int m0 = blockIdx.y * 128, n0 = blockIdx.x * 128;
    const int warp_m = wid & 1, warp_n = wid >> 1;

    const char* pAh = (const char*)(Ah + (size_t)z * batchA);
    const char* pAl = (NPASS == 3) ? (const char*)(Al + (size_t)z * batchA) : nullptr;
    const char* pBh = (const char*)(Bh + (size_t)z * batchB);
    const char* pBl = (NPASS == 3) ? (const char*)(Bl + (size_t)z * batchB) : nullptr;

    const uint32_t sb = smem_u32(smem);
    const uint32_t rowbytes = (uint32_t)K * 2;

    float acc[4][8][4];
#pragma unroll
    for (int t = 0; t < 4; t++)
#pragma unroll
        for (int j = 0; j < 8; j++)
#pragma unroll
            for (int c = 0; c < 4; c++) acc[t][j][c] = 0.0f;

    const int nch = K >> 5;

#define ISSUE(kc, buf)                                                           \
    {                                                                            \
        uint32_t s0 = sb + (buf) * STB;                                          \
        uint32_t kcb = (uint32_t)(kc) * 64;                                      \
        _Pragma("unroll")                                                        \
        for (int i = 0; i < 4; i++) {                                            \
            int c = tid + i * 128;                                               \
            int r = c >> 2, ch = c & 3;                                          \
            size_t goA = (size_t)(m0 + r) * rowbytes + kcb + ch * 16;            \
            size_t goB = (size_t)(n0 + r) * rowbytes + kcb + ch * 16;            \
            uint32_t so = swz(r, ch);                                            \
            cpasync16(s0 + so, pAh + goA);                                       \
            if (NPASS == 3) cpasync16(s0 + TILE + so, pAl + goA);                \
            cpasync16(s0 + BOFF + so, pBh + goB);                                \
            if (NPASS == 3) cpasync16(s0 + 3 * TILE + so, pBl + goB);            \
        }                                                                        \
        asm volatile("cp.async.commit_group;" ::: "memory");                     \
    }

#pragma unroll
    for (int p = 0; p < NSTAGE - 1; p++) ISSUE(p, p);

    int cb = 0, ib = NSTAGE - 1;
    for (int kc = 0; kc < nch; kc++) {
        asm volatile("cp.async.wait_group %0;" :: "n"(NSTAGE - 2) : "memory");
        __syncthreads();

        const int knext = kc + NSTAGE - 1;
        if (knext < nch) ISSUE(knext, ib);
        ib = (ib + 1 == NSTAGE) ? 0 : ib + 1;

        const uint32_t sA = sb + cb * STB;
        cb = (cb + 1 == NSTAGE) ? 0 : cb + 1;

#pragma unroll
        for (int ks = 0; ks < 2; ks++) {
            uint32_t afh[4][4], afl[4][4];

            const int ra0 = warp_m * 64 + (lane & 15);
            const int ca = ks * 2 + (lane >> 4);
#pragma unroll
            for (int t = 0; t < 4; t++) {
                uint32_t ad = sA + swz(ra0 + t * 16, ca);
                ldmx4(afh[t], ad);
                if (NPASS == 3) ldmx4(afl[t], ad + TILE);
            }

            const int rb0 = warp_n * 64 + (lane >> 4) * 8 + (lane & 7);
            const int cbk = ks * 2 + ((lane >> 3) & 1);
#pragma unroll
            for (int jp = 0; jp < 4; jp++) {
                uint32_t bd = sA + BOFF + swz(rb0 + jp * 16, cbk);
                uint32_t rh[4];
                ldmx4(rh, bd);
                const int j0 = jp * 2, j1 = jp * 2 + 1;
#pragma unroll
                for (int t = 0; t < 4; t++) {
                    mma_f16(acc[t][j0], afh[t], rh + 0);
                    mma_f16(acc[t][j1], afh[t], rh + 2);
                }
                if (NPASS == 3) {
                    uint32_t rl[4];
                    ldmx4(rl, bd + TILE);
#pragma unroll
                    for (int t = 0; t < 4; t++) {
                        mma_f16(acc[t][j0], afh[t], rl + 0);
                        mma_f16(acc[t][j1], afh[t], rl + 2);
                    }
#pragma unroll
                    for (int t = 0; t < 4; t++) {
                        mma_f16(acc[t][j0], afl[t], rh + 0);
                        mma_f16(acc[t][j1], afl[t], rh + 2);
                    }
                }
            }
        }
        __syncthreads();
    }
#undef ISSUE

    // fp32 epilogue
    const int rbase = warp_m * 64 + (lane >> 2);
    const int cbase = warp_n * 64 + (lane & 3) * 2;
    float* C = O + (size_t)z * batchC;
#pragma unroll
    for (int t = 0; t < 4; t++)
#pragma unroll
        for (int j = 0; j < 8; j++) {
            int rr = m0 + rbase + t * 16;
            int cc = n0 + cbase + j * 8;
            *(float2*)(C + (size_t)rr * ldC + cc) =
                make_float2(acc[t][j][0], acc[t][j][1]);
            *(float2*)(C + (size_t)(rr + 8) * ldC + cc) =
                make_float2(acc[t][j][2], acc[t][j][3]);
        }
}

// ---------------- prep kernels ----------------------------------------------
__global__ void split_kernel(const float* __restrict__ X,
                             f16* __restrict__ H, f16* __restrict__ L, int n)
{
    int i = blockIdx.x * 256 + threadIdx.x;
    if (i < n) {
        float x = X[i];
        f16 h = __float2half(x);
        H[i] = h;
        L[i] = __float2half(x - __half2float(h));
    }
}

// All three weights transposed+split in ONE launch.
__global__ void wsplit3_kernel(const float* __restrict__ Wq,
                               const float* __restrict__ Wk,
                               const float* __restrict__ Wv,
                               f16* __restrict__ TH, f16* __restrict__ TL)
{
    int i = blockIdx.x * 256 + threadIdx.x;     // 0 .. 3*DIM*DIM-1
    int w = i / (DIM * DIM);
    int r = i - w * (DIM * DIM);                // out idx f*DIM + d within weight
    int f = r / DIM, d = r - f * DIM;
    const float* W = (w == 0) ? Wq : (w == 1) ? Wk : Wv;
    float x = W[d * DIM + f];
    f16 h = __float2half(x);
    TH[i] = h;
    TL[i] = __float2half(x - __half2float(h));
}

// ---------------- softmax: S fp32 -> P fp16 hi (vectorized) -----------------
__global__ void __launch_bounds__(256)
softmax_kernel(const float* __restrict__ S, f16* __restrict__ Ph)
{
    const int row = blockIdx.x;
    const float4* p4 = (const float4*)(S + (size_t)row * SEQ);
    const int tid = threadIdx.x;

    float4 va = p4[tid];
    float4 vb = p4[tid + 256];
    float m = fmaxf(fmaxf(fmaxf(va.x, va.y), fmaxf(va.z, va.w)),
                    fmaxf(fmaxf(vb.x, vb.y), fmaxf(vb.z, vb.w)));

    __shared__ float red[256];
    red[tid] = m;
    __syncthreads();
#pragma unroll
    for (int s = 128; s > 0; s >>= 1) {
        if (tid < s) red[tid] = fmaxf(red[tid], red[tid + s]);
        __syncthreads();
    }
    m = red[0];
    __syncthreads();

    va.x = expf(va.x - m); va.y = expf(va.y - m);
    va.z = expf(va.z - m); va.w = expf(va.w - m);
    vb.x = expf(vb.x - m); vb.y = expf(vb.y - m);
    vb.z = expf(vb.z - m); vb.w = expf(vb.w - m);
    float sum = (va.x + va.y) + (va.z + va.w) + (vb.x + vb.y) + (vb.z + vb.w);

    red[tid] = sum;
    __syncthreads();
#pragma unroll
    for (int s = 128; s > 0; s >>= 1) {
        if (tid < s) red[tid] += red[tid + s];
        __syncthreads();
    }
    const float inv = 1.0f / red[0];

    __half2* ph2 = (__half2*)(Ph + (size_t)row * SEQ);
#pragma unroll
    for (int half = 0; half < 2; half++) {
        float4 v = half ? vb : va;
        int base = (half ? (tid + 256) : tid) * 2;
        ph2[base + 0] = __halves2half2(__float2half(v.x * inv),
                                       __float2half(v.y * inv));
        ph2[base + 1] = __halves2half2(__float2half(v.z * inv),
                                       __float2half(v.w * inv));
    }
}

// ---------------------------------------------------------------------------
extern "C" void kernel_launch(void* const* d_in, const int* in_sizes, int n_in,
                              void* d_out, int out_size)
{
    const float* X  = (const float*)d_in[0];
    const float* Wq = (const float*)d_in[1];
    const float* Wk = (const float*)d_in[2];
    const float* Wv = (const float*)d_in[3];
    float* out = (float*)d_out;

    f16 *xh, *xl, *wth, *wtl, *qh, *ql, *kh, *kl, *vth, *ph;
    float* s;
    cudaGetSymbolAddress((void**)&xh, g_xh);
    cudaGetSymbolAddress((void**)&xl, g_xl);
    cudaGetSymbolAddress((void**)&wth, g_wth);
    cudaGetSymbolAddress((void**)&wtl, g_wtl);
    cudaGetSymbolAddress((void**)&qh, g_qh);
    cudaGetSymbolAddress((void**)&ql, g_ql);
    cudaGetSymbolAddress((void**)&kh, g_kh);
    cudaGetSymbolAddress((void**)&kl, g_kl);
    cudaGetSymbolAddress((void**)&vth, g_vth);
    cudaGetSymbolAddress((void**)&ph, g_ph);
    cudaGetSymbolAddress((void**)&s, g_s);

    cudaFuncSetAttribute(proj_fused, cudaFuncAttributeMaxDynamicSharedMemorySize, SMEMSZ3);
    cudaFuncSetAttribute(gemm_mma<3, 3>, cudaFuncAttributeMaxDynamicSharedMemorySize, SMEMSZ3);
    cudaFuncSetAttribute(gemm_mma<1, 6>, cudaFuncAttributeMaxDynamicSharedMemorySize, SMEMSZ1);

    const int nx = MTOT * DIM;
    split_kernel<<<nx / 256, 256>>>(X, xh, xl, nx);
    wsplit3_kernel<<<(3 * DIM * DIM) / 256, 256>>>(Wq, Wk, Wv, wth, wtl);

    // Fused QKV projection: grid 18 x 128
    dim3 gp(3 * DIM / 128, MTOT / 128, 1);
    proj_fused<<<gp, 128, SMEMSZ3>>>(xh, xl, wth, wtl, qh, ql, kh, kl, vth);

    // Scores: per batch S = Q * K^T, [2048,2048], K=768 (3-pass, 3-stage)
    dim3 gs(SEQ / 128, SEQ / 128, BSZ);
    gemm_mma<3, 3><<<gs, 128, SMEMSZ3>>>(qh, ql, kh, kl, s, DIM,
                                         (long)SEQ * DIM, (long)SEQ * DIM,
                                         (long)SEQ * SEQ, SEQ);

    softmax_kernel<<<BSZ * SEQ, 256>>>(s, ph);

    // Out: per batch O = P * (V^T)^T, [2048,768], K=2048 (1-pass, 6-stage)
    dim3 go(DIM / 128, SEQ / 128, BSZ);
    gemm_mma<1, 6><<<go, 128, SMEMSZ1>>>(ph, nullptr, vth, nullptr, out, SEQ,
                                         (long)SEQ * SEQ, (long)DIM * SEQ,
                                         (long)SEQ * DIM, DIM);
}